// round 14
// baseline (speedup 1.0000x reference)
#include <cuda_runtime.h>

#define Bc 8
#define Sc 1048576
#define Cc 4
#define GW 4
#define GH 4
#define NP 16
#define PW 128
#define PH 128

#define CH 2048                 // events per chunk (one block)
#define CPB (Sc/CH)             // 512 chunks per batch
#define PRE 72                  // prefix chunks counted+scattered (11-sigma margin)
#define FULL 0xffffffffu

#define TAG_MASK 0x60000000u    // [30]=AGG-valid [29]=epoch
#define VAL_MASK 0x1FFFFFFFu
#define TAG_AGG  0x40000000u

// Scratch: epoch-tagged, never reset. Layout: [b][g][chunk] (transposed).
__device__ unsigned g_state[Bc * NP * PRE];
__device__ unsigned g_tick[Bc];      // monotonic; amLast = (t % PRE)==PRE-1
__device__ unsigned g_epoch[Bc];     // flipped by last-ticket block each call

__device__ __forceinline__ int patch_of(float x, float y) {
    int px = min(GW - 1, ((int)x) >> 7);    // coords are non-negative integer-valued
    int py = min(GH - 1, ((int)y) >> 7);
    return (py << 2) | px;
}

__device__ __forceinline__ unsigned sel_mask(int G, unsigned b0, unsigned b1,
                                             unsigned b2, unsigned b3) {
    unsigned m = (G & 1) ? b0 : ~b0;
    m &= (G & 2) ? b1 : ~b1;
    m &= (G & 4) ? b2 : ~b2;
    m &= (G & 8) ? b3 : ~b3;
    return m;
}

// Poll-sum AGGs of chunks [0,n) for groups 2w and 2w+1; result into dst[g].
__device__ __forceinline__ void poll_sum(const unsigned* bstate, int n,
                                         unsigned tagA, int lane, int w,
                                         unsigned* dst) {
#pragma unroll
    for (int half = 0; half < 2; half++) {
        int g = 2 * w + half;
        const unsigned* base = bstate + g * PRE;
        unsigned sum;
        for (;;) {
            sum = 0;
            int ok = 1;
            for (int c0 = 0; c0 < n; c0 += 32) {
                int cc = c0 + lane;
                if (cc < n) {
                    unsigned wd = *(volatile const unsigned*)&base[cc];
                    if ((wd & TAG_MASK) != tagA) ok = 0;
                    sum += wd & VAL_MASK;
                }
            }
            if (__all_sync(FULL, ok)) break;
        }
#pragma unroll
        for (int off = 16; off; off >>= 1)
            sum += __shfl_down_sync(FULL, sum, off);
        if (lane == 0) dst[g] = sum;
    }
}

// Improbable (11-sigma) sequential tail for an unsaturated batch + tail-fill.
__device__ __noinline__ void cold_tail(const float4* __restrict__ ev,
                                       float4* __restrict__ outEv,
                                       float* __restrict__ outMask,
                                       int b, int L, unsigned* run) {
    int tid = threadIdx.x, lane = tid & 31, w = tid >> 5;
    __shared__ unsigned wc2[8][NP];
    int own = lane & 15;
    unsigned lt = (1u << lane) - 1u;
    int b16 = b * NP;
    for (int c2 = PRE; c2 < CPB; c2++) {
        long base2 = (long)b * Sc + (long)c2 * CH + w * 256;
        float4 u[8];
#pragma unroll
        for (int j = 0; j < 8; j++) u[j] = ev[base2 + j * 32 + lane];
        unsigned gp2 = 0, wcnt2 = 0;
#pragma unroll
        for (int j = 0; j < 8; j++) {
            int g = patch_of(u[j].x, u[j].y);
            gp2 |= (unsigned)g << (4 * j);
            unsigned b0 = __ballot_sync(FULL, g & 1);
            unsigned b1 = __ballot_sync(FULL, g & 2);
            unsigned b2 = __ballot_sync(FULL, g & 4);
            unsigned b3 = __ballot_sync(FULL, g & 8);
            wcnt2 += (unsigned)__popc(sel_mask(own, b0, b1, b2, b3));
        }
        if (lane < NP) wc2[w][lane] = wcnt2;
        __syncthreads();
        unsigned bb2 = 0;
        if (lane < NP) {
            bb2 = run[lane];
#pragma unroll
            for (int w2 = 0; w2 < 8; w2++)
                if (w2 < w) bb2 += wc2[w2][lane];
        }
        unsigned rw2 = 0;
#pragma unroll
        for (int j = 0; j < 8; j++) {
            int g = (gp2 >> (4 * j)) & 15;
            unsigned b0 = __ballot_sync(FULL, g & 1);
            unsigned b1 = __ballot_sync(FULL, g & 2);
            unsigned b2 = __ballot_sync(FULL, g & 4);
            unsigned b3 = __ballot_sync(FULL, g & 8);
            unsigned m = sel_mask(g, b0, b1, b2, b3);
            unsigned r = (unsigned)__popc(m & lt);
            unsigned bw = __shfl_sync(FULL, bb2 + rw2, g);
            unsigned rank = bw + r;
            if (rank < (unsigned)L) {
                int px = g & 3, py = g >> 2;
                long row = (long)(b16 + g) * L + rank;
                outEv[row] = make_float4(u[j].x - (float)(px * PW),
                                         u[j].y - (float)(py * PH), u[j].z, u[j].w);
                outMask[row] = 1.0f;
            }
            rw2 += (unsigned)__popc(sel_mask(own, b0, b1, b2, b3));
        }
        __syncthreads();
        if (tid < NP) {
            unsigned s = 0;
#pragma unroll
            for (int w2 = 0; w2 < 8; w2++) s += wc2[w2][tid];
            run[tid] += s;
        }
        __syncthreads();
    }
    for (int g = 0; g < NP; g++) {
        unsigned t = run[g];
        if (t < (unsigned)L) {
            long rowBase = (long)(b * NP + g) * L;
            for (int r = (int)t + tid; r < L; r += 256) {
                outEv[rowBase + r] = make_float4(0.f, 0.f, 0.f, 0.f);
                outMask[rowBase + r] = 0.f;
            }
        }
    }
}

__global__ void __launch_bounds__(256, 4)
fused_main(const float4* __restrict__ ev, float4* __restrict__ outEv,
           float* __restrict__ outMask, int L) {
    int b = blockIdx.x / PRE, c = blockIdx.x % PRE;
    int tid = threadIdx.x, lane = tid & 31, w = tid >> 5;

    __shared__ unsigned wc[8][NP], acc[NP], exc[NP], run[NP];
    __shared__ int amLast_s, anyopen_s;

    unsigned e = (*(volatile unsigned*)&g_epoch[b]) & 1u;
    unsigned tagA = TAG_AGG | (e << 29);
    unsigned* bstate = &g_state[b * NP * PRE];

    // ---- Phase A: xy-only read; count + per-event warp-local offsets ----
    const float4* evb = ev + (long)b * Sc + (long)c * CH;
    int idx0 = w * 256 + lane;
    int own = lane & 15;

    float2 p[8];
#pragma unroll
    for (int j = 0; j < 8; j++)
        p[j] = *(const float2*)(evb + idx0 + j * 32);   // x,y only; full MLP

    unsigned lt = (1u << lane) - 1u;
    unsigned gpack = 0;
    unsigned long long offpack = 0ull;
    unsigned rw = 0;                                     // lanes' own-group counter
#pragma unroll
    for (int j = 0; j < 8; j++) {
        int g = patch_of(p[j].x, p[j].y);
        gpack |= (unsigned)g << (4 * j);
        unsigned b0 = __ballot_sync(FULL, g & 1);
        unsigned b1 = __ballot_sync(FULL, g & 2);
        unsigned b2 = __ballot_sync(FULL, g & 4);
        unsigned b3 = __ballot_sync(FULL, g & 8);
        unsigned m = sel_mask(g, b0, b1, b2, b3);
        unsigned r = (unsigned)__popc(m & lt);
        unsigned off = __shfl_sync(FULL, rw, g) + r;     // warp-local stable offset
        offpack |= (unsigned long long)(off & 0xffu) << (8 * j);
        rw += (unsigned)__popc(sel_mask(own, b0, b1, b2, b3));
    }
    if (lane < NP) wc[w][lane] = rw;
    __syncthreads();

    // ---- Publish AGG (transposed layout); keep block totals in shared ----
    if (tid < NP) {
        unsigned s = 0;
#pragma unroll
        for (int w2 = 0; w2 < 8; w2++) s += wc[w2][tid];
        acc[tid] = s;
        *(volatile unsigned*)&bstate[tid * PRE + c] = s | tagA;
    }
    __syncthreads();                         // all 16 publishes issued

    // ---- Ticket (no fence; all later reads are poll-based) ----
    if (tid == 0) {
        unsigned t = atomicAdd(&g_tick[b], 1u);
        amLast_s = ((t % PRE) == PRE - 1);
        anyopen_s = 0;
    }

    // ---- Exclusive prefix: direct poll-sum of predecessor AGGs ----
    if (c == 0) {
        if (tid < NP) exc[tid] = 0;
    } else {
        poll_sum(bstate, c, tagA, lane, w, exc);
    }
    __syncthreads();
    if (tid < NP && exc[tid] < (unsigned)L) anyopen_s = 1;
    __syncthreads();

    if (anyopen_s) {
        // ---- Phase B: re-read float4 (L1 hit); event stores only ----
        unsigned bb = 0;
        if (lane < NP) {
            bb = exc[lane];
#pragma unroll
            for (int w2 = 0; w2 < 8; w2++)
                if (w2 < w) bb += wc[w2][lane];
        }
        int b16 = b * NP;
#pragma unroll
        for (int j = 0; j < 8; j++) {
            int g = (gpack >> (4 * j)) & 15;
            unsigned bw = __shfl_sync(FULL, bb, g);
            unsigned rank = bw + (unsigned)((offpack >> (8 * j)) & 0xffu);
            if (rank < (unsigned)L) {
                float4 v = evb[idx0 + j * 32];
                int px = g & 3, py = g >> 2;
                long row = (long)(b16 + g) * L + rank;
                outEv[row] = make_float4(v.x - (float)(px * PW),
                                         v.y - (float)(py * PH), v.z, v.w);
            }
        }

        // ---- Coalesced mask fill: this block's contiguous span per group ----
#pragma unroll 1
        for (int g = 0; g < NP; g++) {
            unsigned st = min(exc[g], (unsigned)L);
            unsigned en = min(exc[g] + acc[g], (unsigned)L);
            long rowBase = (long)(b16 + g) * L;
            for (unsigned r = st + tid; r < en; r += 256)
                outMask[rowBase + r] = 1.0f;
        }
    }

    // ---- Last-ticket duties: poll batch totals, improbable cold path, epoch flip ----
    if (!amLast_s) return;

    poll_sum(bstate, PRE, tagA, lane, w, run);
    __syncthreads();

    int sat = 1;
#pragma unroll
    for (int g2 = 0; g2 < NP; g2++)
        if (run[g2] < (unsigned)L) sat = 0;
    if (!sat)
        cold_tail(ev, outEv, outMask, b, L, run);
    __syncthreads();
    if (tid == 0)
        *(volatile unsigned*)&g_epoch[b] = e ^ 1u;   // kernel boundary orders replays
}

extern "C" void kernel_launch(void* const* d_in, const int* in_sizes, int n_in,
                              void* d_out, int out_size) {
    const float4* ev = (const float4*)d_in[0];
    float* out = (float*)d_out;

    int L = out_size / (Bc * NP * (Cc + 1));     // 8192
    float4* outEv = (float4*)out;
    float* outMask = out + (long)Bc * NP * L * Cc;

    fused_main<<<Bc * PRE, 256>>>(ev, outEv, outMask, L);
}

// round 15
// speedup vs baseline: 1.0087x; 1.0087x over previous
#include <cuda_runtime.h>

#define Bc 8
#define Sc 1048576
#define Cc 4
#define GW 4
#define GH 4
#define NP 16
#define PW 128
#define PH 128

#define CH 2048                 // events per chunk (one block)
#define CPB (Sc/CH)             // 512 chunks per batch
#define PRE 68                  // prefix chunks counted+scattered (5.6-sigma margin)
#define FULL 0xffffffffu

#define TAG_MASK 0x60000000u    // [30]=AGG-valid [29]=epoch
#define VAL_MASK 0x1FFFFFFFu
#define TAG_AGG  0x40000000u

// Scratch: epoch-tagged, never reset. Layout: [b][g][chunk] (transposed).
__device__ unsigned g_state[Bc * NP * PRE];
__device__ unsigned g_tick[Bc];      // monotonic; amLast = (t % PRE)==PRE-1
__device__ unsigned g_epoch[Bc];     // flipped by last-ticket block each call

__device__ __forceinline__ int patch_of(float x, float y) {
    int px = min(GW - 1, ((int)x) >> 7);    // coords are non-negative integer-valued
    int py = min(GH - 1, ((int)y) >> 7);
    return (py << 2) | px;
}

__device__ __forceinline__ unsigned sel_mask(int G, unsigned b0, unsigned b1,
                                             unsigned b2, unsigned b3) {
    unsigned m = (G & 1) ? b0 : ~b0;
    m &= (G & 2) ? b1 : ~b1;
    m &= (G & 4) ? b2 : ~b2;
    m &= (G & 8) ? b3 : ~b3;
    return m;
}

// Poll-sum AGGs of chunks [0,n) for groups 2w and 2w+1; result into dst[g].
__device__ __forceinline__ void poll_sum(const unsigned* bstate, int n,
                                         unsigned tagA, int lane, int w,
                                         unsigned* dst) {
#pragma unroll
    for (int half = 0; half < 2; half++) {
        int g = 2 * w + half;
        const unsigned* base = bstate + g * PRE;
        unsigned sum;
        for (;;) {
            sum = 0;
            int ok = 1;
            for (int c0 = 0; c0 < n; c0 += 32) {
                int cc = c0 + lane;
                if (cc < n) {
                    unsigned wd = *(volatile const unsigned*)&base[cc];
                    if ((wd & TAG_MASK) != tagA) ok = 0;
                    sum += wd & VAL_MASK;
                }
            }
            if (__all_sync(FULL, ok)) break;
        }
#pragma unroll
        for (int off = 16; off; off >>= 1)
            sum += __shfl_down_sync(FULL, sum, off);
        if (lane == 0) dst[g] = sum;
    }
}

// Improbable (5.6-sigma) sequential tail for an unsaturated batch + tail-fill.
__device__ __noinline__ void cold_tail(const float4* __restrict__ ev,
                                       float4* __restrict__ outEv,
                                       float* __restrict__ outMask,
                                       int b, int L, unsigned* run) {
    int tid = threadIdx.x, lane = tid & 31, w = tid >> 5;
    __shared__ unsigned wc2[8][NP];
    int own = lane & 15;
    unsigned lt = (1u << lane) - 1u;
    int b16 = b * NP;
    for (int c2 = PRE; c2 < CPB; c2++) {
        long base2 = (long)b * Sc + (long)c2 * CH + w * 256;
        float4 u[8];
#pragma unroll
        for (int j = 0; j < 8; j++) u[j] = ev[base2 + j * 32 + lane];
        unsigned gp2 = 0, wcnt2 = 0;
#pragma unroll
        for (int j = 0; j < 8; j++) {
            int g = patch_of(u[j].x, u[j].y);
            gp2 |= (unsigned)g << (4 * j);
            unsigned b0 = __ballot_sync(FULL, g & 1);
            unsigned b1 = __ballot_sync(FULL, g & 2);
            unsigned b2 = __ballot_sync(FULL, g & 4);
            unsigned b3 = __ballot_sync(FULL, g & 8);
            wcnt2 += (unsigned)__popc(sel_mask(own, b0, b1, b2, b3));
        }
        if (lane < NP) wc2[w][lane] = wcnt2;
        __syncthreads();
        unsigned bb2 = 0;
        if (lane < NP) {
            bb2 = run[lane];
#pragma unroll
            for (int w2 = 0; w2 < 8; w2++)
                if (w2 < w) bb2 += wc2[w2][lane];
        }
        unsigned rw2 = 0;
#pragma unroll
        for (int j = 0; j < 8; j++) {
            int g = (gp2 >> (4 * j)) & 15;
            unsigned b0 = __ballot_sync(FULL, g & 1);
            unsigned b1 = __ballot_sync(FULL, g & 2);
            unsigned b2 = __ballot_sync(FULL, g & 4);
            unsigned b3 = __ballot_sync(FULL, g & 8);
            unsigned m = sel_mask(g, b0, b1, b2, b3);
            unsigned r = (unsigned)__popc(m & lt);
            unsigned bw = __shfl_sync(FULL, bb2 + rw2, g);
            unsigned rank = bw + r;
            if (rank < (unsigned)L) {
                int px = g & 3, py = g >> 2;
                long row = (long)(b16 + g) * L + rank;
                outEv[row] = make_float4(u[j].x - (float)(px * PW),
                                         u[j].y - (float)(py * PH), u[j].z, u[j].w);
                outMask[row] = 1.0f;
            }
            rw2 += (unsigned)__popc(sel_mask(own, b0, b1, b2, b3));
        }
        __syncthreads();
        if (tid < NP) {
            unsigned s = 0;
#pragma unroll
            for (int w2 = 0; w2 < 8; w2++) s += wc2[w2][tid];
            run[tid] += s;
        }
        __syncthreads();
    }
    for (int g = 0; g < NP; g++) {
        unsigned t = run[g];
        if (t < (unsigned)L) {
            long rowBase = (long)(b * NP + g) * L;
            for (int r = (int)t + tid; r < L; r += 256) {
                outEv[rowBase + r] = make_float4(0.f, 0.f, 0.f, 0.f);
                outMask[rowBase + r] = 0.f;
            }
        }
    }
}

__global__ void __launch_bounds__(256, 4)
fused_main(const float4* __restrict__ ev, float4* __restrict__ outEv,
           float* __restrict__ outMask, int L) {
    int b = blockIdx.x / PRE, c = blockIdx.x % PRE;
    int tid = threadIdx.x, lane = tid & 31, w = tid >> 5;

    __shared__ unsigned wc[8][NP], exc[NP], run[NP];
    __shared__ int amLast_s;

    unsigned e = (*(volatile unsigned*)&g_epoch[b]) & 1u;
    unsigned tagA = TAG_AGG | (e << 29);
    unsigned* bstate = &g_state[b * NP * PRE];

    // ---- Phase A: xy-only read; count + per-event warp-local offsets ----
    const float4* evb = ev + (long)b * Sc + (long)c * CH;
    int idx0 = w * 256 + lane;
    int own = lane & 15;

    float2 p[8];
#pragma unroll
    for (int j = 0; j < 8; j++)
        p[j] = *(const float2*)(evb + idx0 + j * 32);   // x,y only; full MLP

    unsigned lt = (1u << lane) - 1u;
    unsigned gpack = 0;
    unsigned long long offpack = 0ull;
    unsigned rw = 0;                                     // lanes' own-group counter
#pragma unroll
    for (int j = 0; j < 8; j++) {
        int g = patch_of(p[j].x, p[j].y);
        gpack |= (unsigned)g << (4 * j);
        unsigned b0 = __ballot_sync(FULL, g & 1);
        unsigned b1 = __ballot_sync(FULL, g & 2);
        unsigned b2 = __ballot_sync(FULL, g & 4);
        unsigned b3 = __ballot_sync(FULL, g & 8);
        unsigned m = sel_mask(g, b0, b1, b2, b3);
        unsigned r = (unsigned)__popc(m & lt);
        unsigned off = __shfl_sync(FULL, rw, g) + r;     // warp-local stable offset
        offpack |= (unsigned long long)(off & 0xffu) << (8 * j);
        rw += (unsigned)__popc(sel_mask(own, b0, b1, b2, b3));
    }
    if (lane < NP) wc[w][lane] = rw;
    __syncthreads();

    // ---- Publish AGG (transposed layout) ----
    if (tid < NP) {
        unsigned s = 0;
#pragma unroll
        for (int w2 = 0; w2 < 8; w2++) s += wc[w2][tid];
        *(volatile unsigned*)&bstate[tid * PRE + c] = s | tagA;
    }
    __syncthreads();                         // all 16 publishes issued

    // ---- Ticket (no fence; all later reads are poll-based) ----
    if (tid == 0) {
        unsigned t = atomicAdd(&g_tick[b], 1u);
        amLast_s = ((t % PRE) == PRE - 1);
    }

    // ---- Exclusive prefix: direct poll-sum of predecessor AGGs ----
    if (c == 0) {
        if (tid < NP) exc[tid] = 0;
    } else {
        poll_sum(bstate, c, tagA, lane, w, exc);
    }
    __syncthreads();
    int anyopen = __syncthreads_or(tid < NP && exc[tid] < (unsigned)L);

    // ---- Phase B: re-read float4 (L1 hit), rank = base + precomputed offset ----
    if (anyopen) {
        unsigned bb = 0;
        if (lane < NP) {
            bb = exc[lane];
#pragma unroll
            for (int w2 = 0; w2 < 8; w2++)
                if (w2 < w) bb += wc[w2][lane];
        }
        int b16 = b * NP;
#pragma unroll
        for (int j = 0; j < 8; j++) {
            int g = (gpack >> (4 * j)) & 15;
            unsigned bw = __shfl_sync(FULL, bb, g);
            unsigned rank = bw + (unsigned)((offpack >> (8 * j)) & 0xffu);
            if (rank < (unsigned)L) {
                float4 v = evb[idx0 + j * 32];
                int px = g & 3, py = g >> 2;
                long row = (long)(b16 + g) * L + rank;
                outEv[row] = make_float4(v.x - (float)(px * PW),
                                         v.y - (float)(py * PH), v.z, v.w);
                outMask[row] = 1.0f;
            }
        }
    }

    // ---- Last-ticket duties: poll batch totals, improbable cold path, epoch flip ----
    if (!amLast_s) return;

    poll_sum(bstate, PRE, tagA, lane, w, run);
    __syncthreads();

    int sat = 1;
#pragma unroll
    for (int g2 = 0; g2 < NP; g2++)
        if (run[g2] < (unsigned)L) sat = 0;
    if (!sat)
        cold_tail(ev, outEv, outMask, b, L, run);
    __syncthreads();
    if (tid == 0)
        *(volatile unsigned*)&g_epoch[b] = e ^ 1u;   // kernel boundary orders replays
}

extern "C" void kernel_launch(void* const* d_in, const int* in_sizes, int n_in,
                              void* d_out, int out_size) {
    const float4* ev = (const float4*)d_in[0];
    float* out = (float*)d_out;

    int L = out_size / (Bc * NP * (Cc + 1));     // 8192
    float4* outEv = (float4*)out;
    float* outMask = out + (long)Bc * NP * L * Cc;

    fused_main<<<Bc * PRE, 256>>>(ev, outEv, outMask, L);
}